// round 1
// baseline (speedup 1.0000x reference)
#include <cuda_runtime.h>
#include <math_constants.h>
#include <cstddef>

// Problem dims (fixed by reference)
#define B_SZ  4096
#define T_SZ  200
#define D_SZ  64
#define H1_SZ 80
#define H2_SZ 40

// Precomputed weight folds (static device scratch; no runtime alloc)
__device__ float g_WA[D_SZ * H1_SZ];   // W1[0:64]   - W1[192:256]
__device__ float g_WQ[D_SZ * H1_SZ];   // W1[64:128] + W1[192:256]

typedef unsigned long long u64;

__device__ __forceinline__ u64 pack2(float lo, float hi) {
    u64 r; asm("mov.b64 %0,{%1,%2};" : "=l"(r) : "f"(lo), "f"(hi)); return r;
}
__device__ __forceinline__ u64 dup2(float x) { return pack2(x, x); }
__device__ __forceinline__ u64 ffma2(u64 a, u64 b, u64 c) {
    u64 r; asm("fma.rn.f32x2 %0,%1,%2,%3;" : "=l"(r) : "l"(a), "l"(b), "l"(c)); return r;
}
__device__ __forceinline__ void unpack2(u64 v, float& lo, float& hi) {
    asm("mov.b64 {%0,%1},%2;" : "=f"(lo), "=f"(hi) : "l"(v));
}
__device__ __forceinline__ float sigmoidf_(float x) {
    return 1.0f / (1.0f + __expf(-x));
}

// ---------------------------------------------------------------------------
// prep: fold W1 blocks once per launch (cheap, 5120 threads)
// ---------------------------------------------------------------------------
__global__ void prep_kernel(const float* __restrict__ W1) {
    int i = blockIdx.x * blockDim.x + threadIdx.x;
    if (i < D_SZ * H1_SZ) {
        int d = i / H1_SZ, h = i % H1_SZ;
        float w0  = W1[d * H1_SZ + h];           // fact block
        float wq  = W1[(64 + d) * H1_SZ + h];    // q block
        float wmf = W1[(192 + d) * H1_SZ + h];   // (q - fact) block
        g_WA[i] = w0 - wmf;
        g_WQ[i] = wq + wmf;
    }
}

// ---------------------------------------------------------------------------
// main: one CTA per batch row. 224 threads (7 warps); thread t handles
// timestep t for the MLP; then block softmax; then weighted sum over T.
// ---------------------------------------------------------------------------
__global__ __launch_bounds__(224, 2) void attn_kernel(
    const float* __restrict__ query, const float* __restrict__ fact,
    const int*   __restrict__ mask,  const float* __restrict__ W1,
    const float* __restrict__ b1,    const float* __restrict__ W2,
    const float* __restrict__ b2,    const float* __restrict__ W3,
    const float* __restrict__ b3,    float* __restrict__ out)
{
    __shared__ __align__(16) float sWe[D_SZ * H1_SZ];   // 20480 B  W_eff(b)
    __shared__ __align__(16) float sW2[H1_SZ * H2_SZ];  // 12800 B
    __shared__ __align__(16) float sc1[H1_SZ];          // per-b layer-1 bias
    __shared__ __align__(16) float sb2[H2_SZ];
    __shared__ float sW3[H2_SZ];
    __shared__ float sq[D_SZ];
    __shared__ float ssc[224];                          // scores (padded)
    __shared__ float sw[T_SZ];                          // softmax weights
    __shared__ float sredA[7], sredB[7];
    __shared__ float s_b3;

    const int tid = threadIdx.x;
    const int b   = blockIdx.x;

    // ---- stage per-batch / shared weights ----
    if (tid < D_SZ)                      sq[tid]        = query[b * D_SZ + tid];
    if (tid >= 64  && tid < 64 + H2_SZ)  sW3[tid - 64]  = W3[tid - 64];
    if (tid >= 104 && tid < 104 + H2_SZ) sb2[tid - 104] = b2[tid - 104];
    if (tid == 144)                      s_b3           = b3[0];
    __syncthreads();

    // c1[h] = b1[h] + sum_d q[d] * g_WQ[d][h]
    if (tid < H1_SZ) {
        float acc = b1[tid];
        #pragma unroll
        for (int d = 0; d < D_SZ; d++)
            acc = fmaf(sq[d], g_WQ[d * H1_SZ + tid], acc);
        sc1[tid] = acc;
    }
    for (int i = tid; i < H1_SZ * H2_SZ; i += 224) sW2[i] = W2[i];
    // W_eff[d][h] = g_WA[d][h] + q[d] * W1[128+d][h]
    for (int i = tid; i < D_SZ * H1_SZ; i += 224) {
        int d = i / H1_SZ;
        sWe[i] = fmaf(sq[d], W1[128 * H1_SZ + i], g_WA[i]);
    }
    __syncthreads();

    // ---- per-timestep MLP ----
    int   mreg = 0;
    float e    = 0.0f;
    if (tid < T_SZ) {
        const float4* fr =
            reinterpret_cast<const float4*>(fact + ((size_t)b * T_SZ + tid) * D_SZ);

        u64 acc2[H2_SZ / 2];                      // packed layer-2 pre-acts
        const u64* b2p = reinterpret_cast<const u64*>(sb2);
        #pragma unroll
        for (int k = 0; k < H2_SZ / 2; k++) acc2[k] = b2p[k];

        // two halves of H1 (40 each) to bound register pressure
        #pragma unroll
        for (int half = 0; half < 2; half++) {
            u64 z1[20];
            const u64* c1p = reinterpret_cast<const u64*>(sc1 + half * 40);
            #pragma unroll
            for (int j = 0; j < 20; j++) z1[j] = c1p[j];

            #pragma unroll
            for (int dc = 0; dc < 16; dc++) {
                float4 f4 = fr[dc];
                float fv[4] = {f4.x, f4.y, f4.z, f4.w};
                #pragma unroll
                for (int e4 = 0; e4 < 4; e4++) {
                    u64 a = dup2(fv[e4]);
                    const u64* wp = reinterpret_cast<const u64*>(
                        sWe + (dc * 4 + e4) * H1_SZ + half * 40);
                    #pragma unroll
                    for (int j = 0; j < 20; j++) z1[j] = ffma2(a, wp[j], z1[j]);
                }
            }
            // sigmoid + layer-2 accumulate (consume z1 pairwise)
            #pragma unroll
            for (int j = 0; j < 20; j++) {
                float za, zb; unpack2(z1[j], za, zb);
                float sa  = sigmoidf_(za);
                float sb_ = sigmoidf_(zb);
                int h0 = half * 40 + 2 * j;
                u64 pa = dup2(sa), pb = dup2(sb_);
                const u64* w2a = reinterpret_cast<const u64*>(sW2 + h0 * H2_SZ);
                const u64* w2b = reinterpret_cast<const u64*>(sW2 + (h0 + 1) * H2_SZ);
                #pragma unroll
                for (int k = 0; k < 20; k++)
                    acc2[k] = ffma2(pa, w2a[k], ffma2(pb, w2b[k], acc2[k]));
            }
        }

        // layer 3
        float s = s_b3;
        #pragma unroll
        for (int k = 0; k < 20; k++) {
            float za, zb; unpack2(acc2[k], za, zb);
            s = fmaf(sigmoidf_(za), sW3[2 * k],     s);
            s = fmaf(sigmoidf_(zb), sW3[2 * k + 1], s);
        }

        mreg = mask[b * T_SZ + tid];
        ssc[tid] = (mreg == 1) ? s : -2147483648.0f;   // NEG_BIG = -2^31
    } else {
        ssc[tid] = -CUDART_INF_F;
    }
    __syncthreads();

    // ---- block softmax over T ----
    float v = ssc[tid];
    #pragma unroll
    for (int o = 16; o > 0; o >>= 1)
        v = fmaxf(v, __shfl_xor_sync(0xffffffffu, v, o));
    int wid = tid >> 5, lane = tid & 31;
    if (lane == 0) sredA[wid] = v;
    __syncthreads();
    float mx = sredA[0];
    #pragma unroll
    for (int i = 1; i < 7; i++) mx = fmaxf(mx, sredA[i]);

    if (tid < T_SZ) e = __expf(ssc[tid] - mx);  // all-masked: 0-0 -> e=1 (matches ref)
    float es = e;
    #pragma unroll
    for (int o = 16; o > 0; o >>= 1)
        es += __shfl_xor_sync(0xffffffffu, es, o);
    if (lane == 0) sredB[wid] = es;
    __syncthreads();
    float total = 0.0f;
    #pragma unroll
    for (int i = 0; i < 7; i++) total += sredB[i];

    if (tid < T_SZ) sw[tid] = (mreg == 1) ? (e / total) : 0.0f;
    __syncthreads();

    // ---- weighted sum over history: out[b][d] = sum_t w[t]*fact[b][t][d] ----
    if (tid < D_SZ) {
        const float* fb = fact + (size_t)b * T_SZ * D_SZ + tid;
        float acc = 0.0f;
        #pragma unroll 8
        for (int t = 0; t < T_SZ; t++)
            acc = fmaf(sw[t], fb[t * D_SZ], acc);
        out[b * D_SZ + tid] = acc;
    }
}

extern "C" void kernel_launch(void* const* d_in, const int* in_sizes, int n_in,
                              void* d_out, int out_size)
{
    const float* query = (const float*)d_in[0];
    const float* fact  = (const float*)d_in[1];
    const int*   mask  = (const int*)  d_in[2];
    const float* W1    = (const float*)d_in[3];
    const float* b1    = (const float*)d_in[4];
    const float* W2    = (const float*)d_in[5];
    const float* b2    = (const float*)d_in[6];
    const float* W3    = (const float*)d_in[7];
    const float* b3    = (const float*)d_in[8];
    float* out = (float*)d_out;

    prep_kernel<<<(D_SZ * H1_SZ + 255) / 256, 256>>>(W1);
    attn_kernel<<<B_SZ, 224>>>(query, fact, mask, W1, b1, W2, b2, W3, b3, out);
}

// round 2
// speedup vs baseline: 1.0535x; 1.0535x over previous
#include <cuda_runtime.h>
#include <cooperative_groups.h>
#include <math_constants.h>
#include <cstddef>

namespace cg = cooperative_groups;

#define B_SZ  4096
#define T_SZ  200
#define TH    100     // timesteps per CTA (half a batch row)
#define D_SZ  64
#define H1_SZ 80
#define H2_SZ 40
#define TP    101     // padded stride for sF (conflict-free column reads)
#define NEG_BIG_F (-2147483648.0f)

// Precomputed folds (device scratch; no runtime alloc)
__device__ float g_WA[D_SZ * H1_SZ];   // W1[0:64]  - W1[192:256]
__device__ float g_WQ[D_SZ * H1_SZ];   // W1[64:128]+ W1[192:256]
__device__ float g_C1[B_SZ * H1_SZ];   // per-batch layer-1 bias b1 + q·g_WQ

typedef unsigned long long u64;

__device__ __forceinline__ u64 dup2(float x) {
    u64 r; asm("mov.b64 %0,{%1,%1};" : "=l"(r) : "f"(x)); return r;
}
__device__ __forceinline__ u64 ffma2(u64 a, u64 b, u64 c) {
    u64 r; asm("fma.rn.f32x2 %0,%1,%2,%3;" : "=l"(r) : "l"(a), "l"(b), "l"(c)); return r;
}
__device__ __forceinline__ void unpack2(u64 v, float& lo, float& hi) {
    asm("mov.b64 {%0,%1},%2;" : "=f"(lo), "=f"(hi) : "l"(v));
}
__device__ __forceinline__ float sigmoidf_(float x) {
    return 1.0f / (1.0f + __expf(-x));
}

// ---------------------------------------------------------------------------
// prep 1: fold W1 blocks
// ---------------------------------------------------------------------------
__global__ void prep_fold(const float* __restrict__ W1) {
    int i = blockIdx.x * blockDim.x + threadIdx.x;
    if (i < D_SZ * H1_SZ) {
        int d = i / H1_SZ, h = i % H1_SZ;
        float wf   = W1[d * H1_SZ + h];
        float wq   = W1[(64 + d) * H1_SZ + h];
        float wqmf = W1[(192 + d) * H1_SZ + h];
        g_WA[i] = wf - wqmf;
        g_WQ[i] = wq + wqmf;
    }
}

// ---------------------------------------------------------------------------
// prep 2: per-batch layer-1 bias c1[b][h] = b1[h] + sum_d q[b][d]*g_WQ[d][h]
// ---------------------------------------------------------------------------
__global__ void prep_c1(const float* __restrict__ query, const float* __restrict__ b1) {
    __shared__ float q[D_SZ];
    int b = blockIdx.x;
    if (threadIdx.x < D_SZ) q[threadIdx.x] = query[b * D_SZ + threadIdx.x];
    __syncthreads();
    int h = threadIdx.x;
    if (h < H1_SZ) {
        float acc = b1[h];
        #pragma unroll
        for (int d = 0; d < D_SZ; d++)
            acc = fmaf(q[d], g_WQ[d * H1_SZ + h], acc);
        g_C1[b * H1_SZ + h] = acc;
    }
}

// ---------------------------------------------------------------------------
// main: cluster of 2 CTAs per batch row; each CTA owns 100 timesteps.
// ---------------------------------------------------------------------------
struct __align__(16) SM {
    float sF[D_SZ][TP];          // fact transposed [d][t], padded
    float sWe[D_SZ * H1_SZ];     // per-batch W_eff
    float sW2[H1_SZ * H2_SZ];
    float sh1[H1_SZ][TH];        // sigmoid(layer1) [h][t]
    float sc1[H1_SZ];
    float sW3[H2_SZ];
    float sb2p[H2_SZ];
    float sq[D_SZ];
    float ssP[2][TH];            // layer-3 partial scores (k-halves)
    float ssc[TH];               // masked scores
    float se[TH];                // exp(s - max)
    float swt[TH];               // softmax weights
    float spart[3][D_SZ];        // weighted-sum partials
    float sred[8];
    float xmax, xsum, sb3;
    int   smask[TH];
};

__global__ void __cluster_dims__(2, 1, 1) __launch_bounds__(224, 2)
attn2(const float* __restrict__ query, const float* __restrict__ fact,
      const int*   __restrict__ mask,  const float* __restrict__ W1,
      const float* __restrict__ b1,    const float* __restrict__ W2,
      const float* __restrict__ b2,    const float* __restrict__ W3,
      const float* __restrict__ b3,    float* __restrict__ out)
{
    extern __shared__ __align__(16) char smraw[];
    SM* s = reinterpret_cast<SM*>(smraw);
    const int tid  = threadIdx.x;
    const int b    = blockIdx.x >> 1;
    const int half = blockIdx.x & 1;
    const int t0   = half * TH;
    cg::cluster_group cluster = cg::this_cluster();
    const unsigned peer = (unsigned)(half ^ 1);

    // ---- stage 1: independent loads ----
    if (tid < D_SZ)   s->sq[tid]  = query[b * D_SZ + tid];
    if (tid < H1_SZ)  s->sc1[tid] = g_C1[b * H1_SZ + tid];
    for (int i = tid; i < H1_SZ * H2_SZ; i += 224) s->sW2[i] = W2[i];
    if (tid < H2_SZ)  { s->sW3[tid] = W3[tid]; s->sb2p[tid] = b2[tid]; }
    if (tid == 200)   s->sb3 = b3[0];
    if (tid < TH)     s->smask[tid] = mask[b * T_SZ + t0 + tid];
    {   // fact -> sF transpose (coalesced global float4 reads)
        const float4* fb4 = reinterpret_cast<const float4*>(
            fact + ((size_t)b * T_SZ + t0) * D_SZ);
        for (int i = tid; i < TH * (D_SZ / 4); i += 224) {
            int t = i >> 4, c = i & 15;
            float4 v = fb4[t * 16 + c];
            s->sF[4 * c + 0][t] = v.x;
            s->sF[4 * c + 1][t] = v.y;
            s->sF[4 * c + 2][t] = v.z;
            s->sF[4 * c + 3][t] = v.w;
        }
    }
    __syncthreads();

    // ---- stage 2: W_eff[d][h] = g_WA + q[d]*W1_fq[d][h] ----
    for (int i = tid; i < D_SZ * H1_SZ; i += 224) {
        int d = i / H1_SZ;
        s->sWe[i] = fmaf(s->sq[d], W1[128 * H1_SZ + i], g_WA[i]);
    }
    __syncthreads();

    // ---- phase A: layer 1 (+sigmoid) -> sh1. item = (h-quarter, t-pair) ----
    if (tid < 200) {
        const int hq = tid / 50;
        const int tp = tid % 50;
        const int ta = tp, tb = tp + 50;
        u64 za[10], zb[10];
        {
            const ulonglong2* c1p =
                reinterpret_cast<const ulonglong2*>(s->sc1 + hq * 20);
            #pragma unroll
            for (int j = 0; j < 5; j++) {
                ulonglong2 c = c1p[j];
                za[2*j] = c.x; za[2*j+1] = c.y;
                zb[2*j] = c.x; zb[2*j+1] = c.y;
            }
        }
        const float* wbase = s->sWe + hq * 20;
        #pragma unroll 8
        for (int d = 0; d < D_SZ; d++) {
            u64 a  = dup2(s->sF[d][ta]);
            u64 bb = dup2(s->sF[d][tb]);
            const ulonglong2* wp =
                reinterpret_cast<const ulonglong2*>(wbase + d * H1_SZ);
            #pragma unroll
            for (int j = 0; j < 5; j++) {
                ulonglong2 w = wp[j];
                za[2*j]   = ffma2(a,  w.x, za[2*j]);
                za[2*j+1] = ffma2(a,  w.y, za[2*j+1]);
                zb[2*j]   = ffma2(bb, w.x, zb[2*j]);
                zb[2*j+1] = ffma2(bb, w.y, zb[2*j+1]);
            }
        }
        #pragma unroll
        for (int j = 0; j < 10; j++) {
            float x0, x1;
            int h = hq * 20 + 2 * j;
            unpack2(za[j], x0, x1);
            s->sh1[h][ta]     = sigmoidf_(x0);
            s->sh1[h + 1][ta] = sigmoidf_(x1);
            unpack2(zb[j], x0, x1);
            s->sh1[h][tb]     = sigmoidf_(x0);
            s->sh1[h + 1][tb] = sigmoidf_(x1);
        }
    }
    __syncthreads();

    // ---- phase B: layer 2 (+sigmoid) + layer-3 partial. item=(k-half,t-pair)
    if (tid < 100) {
        const int kh = tid / 50;
        const int tp = tid % 50;
        const int ta = tp, tb = tp + 50;
        u64 aa[10], ab[10];
        {
            const ulonglong2* b2p =
                reinterpret_cast<const ulonglong2*>(s->sb2p + kh * 20);
            #pragma unroll
            for (int j = 0; j < 5; j++) {
                ulonglong2 c = b2p[j];
                aa[2*j] = c.x; aa[2*j+1] = c.y;
                ab[2*j] = c.x; ab[2*j+1] = c.y;
            }
        }
        const float* w2base = s->sW2 + kh * 20;
        #pragma unroll 8
        for (int h = 0; h < H1_SZ; h++) {
            u64 pa = dup2(s->sh1[h][ta]);
            u64 pb = dup2(s->sh1[h][tb]);
            const ulonglong2* wp =
                reinterpret_cast<const ulonglong2*>(w2base + h * H2_SZ);
            #pragma unroll
            for (int j = 0; j < 5; j++) {
                ulonglong2 w = wp[j];
                aa[2*j]   = ffma2(pa, w.x, aa[2*j]);
                aa[2*j+1] = ffma2(pa, w.y, aa[2*j+1]);
                ab[2*j]   = ffma2(pb, w.x, ab[2*j]);
                ab[2*j+1] = ffma2(pb, w.y, ab[2*j+1]);
            }
        }
        float sa = 0.f, sb = 0.f;
        #pragma unroll
        for (int j = 0; j < 10; j++) {
            float x0, x1;
            int k = kh * 20 + 2 * j;
            unpack2(aa[j], x0, x1);
            sa = fmaf(sigmoidf_(x0), s->sW3[k],     sa);
            sa = fmaf(sigmoidf_(x1), s->sW3[k + 1], sa);
            unpack2(ab[j], x0, x1);
            sb = fmaf(sigmoidf_(x0), s->sW3[k],     sb);
            sb = fmaf(sigmoidf_(x1), s->sW3[k + 1], sb);
        }
        s->ssP[kh][ta] = sa;
        s->ssP[kh][tb] = sb;
    }
    __syncthreads();

    // ---- scores + mask ----
    if (tid < TH) {
        float sc = s->sb3 + s->ssP[0][tid] + s->ssP[1][tid];
        s->ssc[tid] = (s->smask[tid] == 1) ? sc : NEG_BIG_F;
    }
    __syncthreads();

    const int lane = tid & 31, wid = tid >> 5;

    // ---- local max -> cluster max ----
    float v = (tid < TH) ? s->ssc[tid] : -CUDART_INF_F;
    #pragma unroll
    for (int o = 16; o > 0; o >>= 1)
        v = fmaxf(v, __shfl_xor_sync(0xffffffffu, v, o));
    if (lane == 0) s->sred[wid] = v;
    __syncthreads();
    if (tid == 0) {
        float m = s->sred[0];
        #pragma unroll
        for (int i = 1; i < 7; i++) m = fmaxf(m, s->sred[i]);
        s->xmax = m;
    }
    cluster.sync();
    float mg;
    {
        const float* px = (const float*)cluster.map_shared_rank((void*)&s->xmax, peer);
        mg = fmaxf(s->xmax, *px);
    }

    // ---- exp + local sum -> cluster sum ----
    float e = 0.f;
    if (tid < TH) { e = __expf(s->ssc[tid] - mg); s->se[tid] = e; }
    float sv = e;
    #pragma unroll
    for (int o = 16; o > 0; o >>= 1)
        sv += __shfl_xor_sync(0xffffffffu, sv, o);
    if (lane == 0) s->sred[wid] = sv;
    __syncthreads();
    if (tid == 0) {
        float t = 0.f;
        #pragma unroll
        for (int i = 0; i < 7; i++) t += s->sred[i];
        s->xsum = t;
    }
    cluster.sync();
    float denom;
    {
        const float* ps = (const float*)cluster.map_shared_rank((void*)&s->xsum, peer);
        denom = s->xsum + *ps;
    }
    if (tid < TH) s->swt[tid] = (s->smask[tid] == 1) ? (s->se[tid] / denom) : 0.f;
    __syncthreads();

    // ---- weighted sum over local timesteps ----
    if (tid < 192) {
        int g = tid >> 6, d = tid & 63;
        int ts = g * 34;
        int te = (g == 2) ? TH : ts + 34;
        float acc = 0.f;
        for (int t = ts; t < te; t++)
            acc = fmaf(s->swt[t], s->sF[d][t], acc);
        s->spart[g][d] = acc;
    }
    __syncthreads();
    if (tid < D_SZ)
        s->spart[0][tid] = s->spart[0][tid] + s->spart[1][tid] + s->spart[2][tid];
    cluster.sync();
    if (half == 0 && tid < D_SZ) {
        const float* pp =
            (const float*)cluster.map_shared_rank((void*)&s->spart[0][0], peer);
        out[b * D_SZ + tid] = s->spart[0][tid] + pp[tid];
    }
    cluster.sync();
}

extern "C" void kernel_launch(void* const* d_in, const int* in_sizes, int n_in,
                              void* d_out, int out_size)
{
    const float* query = (const float*)d_in[0];
    const float* fact  = (const float*)d_in[1];
    const int*   mask  = (const int*)  d_in[2];
    const float* W1    = (const float*)d_in[3];
    const float* b1    = (const float*)d_in[4];
    const float* W2    = (const float*)d_in[5];
    const float* b2    = (const float*)d_in[6];
    const float* W3    = (const float*)d_in[7];
    const float* b3    = (const float*)d_in[8];
    float* out = (float*)d_out;

    cudaFuncSetAttribute(attn2, cudaFuncAttributeMaxDynamicSharedMemorySize,
                         (int)sizeof(SM));

    prep_fold<<<(D_SZ * H1_SZ + 255) / 256, 256>>>(W1);
    prep_c1<<<B_SZ, 96>>>(query, b1);
    attn2<<<B_SZ * 2, 224, sizeof(SM)>>>(query, fact, mask, W1, b1, W2, b2,
                                         W3, b3, out);
}